// round 10
// baseline (speedup 1.0000x reference)
#include <cuda_runtime.h>
#include <math.h>

#define Bn 16
#define Sn 4096
#define Dn 256
#define Nn 16
#define Ln 64
#define Cn (Sn / Ln)   // 64 chunks
#define DTc 1e-4f
#define EPSc 1e-5f

// Scratch (no allocations allowed): local-scan states H [B][C][N][L], chunk
// boundary states, and per-chunk initial states.
__device__ float g_H[(size_t)Bn * Cn * Nn * Ln];   // 4 MB
__device__ float g_hend[Bn * Cn * Nn];
__device__ float g_hstart[Bn * Cn * Nn];

// ---------------------------------------------------------------------------
// Phase 1: per (batch, chunk) block. W = B_d @ U  (N x L GEMM over D=256),
// then local sequential scan h_t = A_d*h_{t-1} + w_t with h_{-1}=0.
// Stores local H and the chunk-final local state.
// ---------------------------------------------------------------------------
__global__ __launch_bounds__(256) void s4_phase1(const float* __restrict__ x,
                                                 const float* __restrict__ A,
                                                 const float* __restrict__ Bm) {
    extern __shared__ float smem[];
    float (*Xs)[Dn + 4] = (float(*)[Dn + 4])smem;                    // 64 x 260
    float (*Bs)[Dn]     = (float(*)[Dn])(smem + Ln * (Dn + 4));      // 16 x 256
    float (*Ws)[Ln + 1] = (float(*)[Ln + 1])(smem + Ln * (Dn + 4) + Nn * Dn);
    float* Ad           = smem + Ln * (Dn + 4) + Nn * Dn + Nn * (Ln + 1);

    int blk = blockIdx.x;
    int b = blk / Cn, c = blk % Cn;
    int tid = threadIdx.x;

    // Stage x chunk (contiguous 64KB) into padded smem, float4.
    const float4* xg = (const float4*)(x + ((size_t)b * Sn + (size_t)c * Ln) * Dn);
    #pragma unroll
    for (int k = 0; k < 16; k++) {
        int i4 = tid + k * 256;
        int t = i4 >> 6, d4 = i4 & 63;
        *(float4*)&Xs[t][d4 * 4] = xg[i4];
    }
    // B_d = DT * Bm
    float* bsf = &Bs[0][0];
    #pragma unroll
    for (int k = 0; k < 16; k++) {
        int i = tid + k * 256;
        bsf[i] = DTc * Bm[i];
    }
    if (tid < Nn) Ad[tid] = (float)exp(-(double)DTc * fabs((double)A[tid]));
    __syncthreads();

    // GEMM: thread = (nq, t); 4 n-accumulators, 256-deep dot via float4.
    // LDS phases are conflict-free: lane row-stride 260 floats -> start bank
    // (4*l) mod 32, 8-lane phases cover all 32 banks exactly once.
    int t  = tid & 63;
    int n0 = (tid >> 6) * 4;
    float a0 = 0.f, a1 = 0.f, a2 = 0.f, a3 = 0.f;
    #pragma unroll 8
    for (int d4 = 0; d4 < 64; d4++) {
        float4 u  = *(const float4*)&Xs[t][d4 * 4];
        float4 b0 = *(const float4*)&Bs[n0 + 0][d4 * 4];
        float4 b1 = *(const float4*)&Bs[n0 + 1][d4 * 4];
        float4 b2 = *(const float4*)&Bs[n0 + 2][d4 * 4];
        float4 b3 = *(const float4*)&Bs[n0 + 3][d4 * 4];
        a0 = fmaf(u.x, b0.x, a0); a0 = fmaf(u.y, b0.y, a0);
        a0 = fmaf(u.z, b0.z, a0); a0 = fmaf(u.w, b0.w, a0);
        a1 = fmaf(u.x, b1.x, a1); a1 = fmaf(u.y, b1.y, a1);
        a1 = fmaf(u.z, b1.z, a1); a1 = fmaf(u.w, b1.w, a1);
        a2 = fmaf(u.x, b2.x, a2); a2 = fmaf(u.y, b2.y, a2);
        a2 = fmaf(u.z, b2.z, a2); a2 = fmaf(u.w, b2.w, a2);
        a3 = fmaf(u.x, b3.x, a3); a3 = fmaf(u.y, b3.y, a3);
        a3 = fmaf(u.z, b3.z, a3); a3 = fmaf(u.w, b3.w, a3);
    }
    Ws[n0 + 0][t] = a0;
    Ws[n0 + 1][t] = a1;
    Ws[n0 + 2][t] = a2;
    Ws[n0 + 3][t] = a3;
    __syncthreads();

    // Local scan (16 lanes, sequential over L=64; tiny).
    if (tid < Nn) {
        int n = tid;
        float a = Ad[n], h = 0.f;
        #pragma unroll
        for (int tt = 0; tt < Ln; tt++) {
            h = fmaf(a, h, Ws[n][tt]);
            Ws[n][tt] = h;
        }
        g_hend[(b * Cn + c) * Nn + n] = h;
    }
    __syncthreads();

    // Coalesced copy-out of local H [n][t].
    size_t base = ((size_t)(b * Cn + c)) * Nn * Ln;
    #pragma unroll
    for (int k = 0; k < 4; k++) {
        int i = tid + k * 256;
        int n = i >> 6, tt = i & 63;
        g_H[base + i] = Ws[n][tt];
    }
}

// ---------------------------------------------------------------------------
// Phase 2: scan across chunks. One block, 256 threads = (b, n).
// hstart[c] = A_d^L * hstart[c-1] + hend_local[c-1],  hstart[0] = 0.
// ---------------------------------------------------------------------------
__global__ __launch_bounds__(256) void s4_phase2(const float* __restrict__ A) {
    int tid = threadIdx.x;
    int b = tid >> 4, n = tid & 15;
    float a = (float)exp(-(double)DTc * fabs((double)A[n]));
    float aL = a;
    #pragma unroll
    for (int i = 0; i < 6; i++) aL *= aL;   // a^64

    float he[Cn];
    #pragma unroll
    for (int c = 0; c < Cn; c++) he[c] = g_hend[(b * Cn + c) * Nn + n];
    float s = 0.f;
    #pragma unroll
    for (int c = 0; c < Cn; c++) {
        g_hstart[(b * Cn + c) * Nn + n] = s;
        s = fmaf(aL, s, he[c]);
    }
}

// ---------------------------------------------------------------------------
// Phase 3: per (batch, chunk) block. Correct H with A^(t+1)*h_start (clip),
// Y = Cm @ H + Dv .* U (clip), LayerNorm over D, write out.
// ---------------------------------------------------------------------------
__global__ __launch_bounds__(256) void s4_phase3(const float* __restrict__ x,
                                                 const float* __restrict__ A,
                                                 const float* __restrict__ Cm,
                                                 const float* __restrict__ Dv,
                                                 const float* __restrict__ gamma,
                                                 const float* __restrict__ beta,
                                                 float* __restrict__ out) {
    extern __shared__ float smem[];
    float (*Xs)[Dn + 4] = (float(*)[Dn + 4])smem;                 // 64 x 260
    float (*Ht)[Nn]     = (float(*)[Nn])(smem + Ln * (Dn + 4));   // 64 x 16 ([t][n])
    float* Adh          = smem + Ln * (Dn + 4) + Ln * Nn;
    float* Hst          = Adh + Nn;

    int blk = blockIdx.x;
    int b = blk / Cn, c = blk % Cn;
    int tid = threadIdx.x;

    const float4* xg = (const float4*)(x + ((size_t)b * Sn + (size_t)c * Ln) * Dn);
    #pragma unroll
    for (int k = 0; k < 16; k++) {
        int i4 = tid + k * 256;
        int t = i4 >> 6, d4 = i4 & 63;
        *(float4*)&Xs[t][d4 * 4] = xg[i4];
    }
    // Load local H, transposed to [t][n].
    size_t base = ((size_t)(b * Cn + c)) * Nn * Ln;
    #pragma unroll
    for (int k = 0; k < 4; k++) {
        int i = tid + k * 256;
        int n = i >> 6, tt = i & 63;
        Ht[tt][n] = g_H[base + i];
    }
    if (tid < Nn) {
        Adh[tid] = (float)exp(-(double)DTc * fabs((double)A[tid]));
        Hst[tid] = g_hstart[(b * Cn + c) * Nn + tid];
    }
    __syncthreads();

    // Correction: h_t = clip(H_local + A^(t+1) * h_start). 16 lanes.
    if (tid < Nn) {
        int n = tid;
        float a = Adh[n], h0 = Hst[n], p = a;
        #pragma unroll
        for (int tt = 0; tt < Ln; tt++) {
            float v = fmaf(p, h0, Ht[tt][n]);
            v = fminf(fmaxf(v, -10.f), 10.f);
            Ht[tt][n] = v;
            p *= a;
        }
    }
    __syncthreads();

    // GEMM2: thread = d. Cm row in registers; Ht rows broadcast via float4.
    int d = tid;
    const float4* cmp = (const float4*)(Cm + d * Nn);
    float4 c0 = cmp[0], c1 = cmp[1], c2 = cmp[2], c3 = cmp[3];
    float dv = Dv[d];
    #pragma unroll 4
    for (int t = 0; t < Ln; t++) {
        float u = Xs[t][d];
        float acc = u * dv;
        const float4* hp = (const float4*)&Ht[t][0];
        float4 h0 = hp[0], h1 = hp[1], h2 = hp[2], h3 = hp[3];
        acc = fmaf(c0.x, h0.x, acc); acc = fmaf(c0.y, h0.y, acc);
        acc = fmaf(c0.z, h0.z, acc); acc = fmaf(c0.w, h0.w, acc);
        acc = fmaf(c1.x, h1.x, acc); acc = fmaf(c1.y, h1.y, acc);
        acc = fmaf(c1.z, h1.z, acc); acc = fmaf(c1.w, h1.w, acc);
        acc = fmaf(c2.x, h2.x, acc); acc = fmaf(c2.y, h2.y, acc);
        acc = fmaf(c2.z, h2.z, acc); acc = fmaf(c2.w, h2.w, acc);
        acc = fmaf(c3.x, h3.x, acc); acc = fmaf(c3.y, h3.y, acc);
        acc = fmaf(c3.z, h3.z, acc); acc = fmaf(c3.w, h3.w, acc);
        acc = fminf(fmaxf(acc, -10.f), 10.f);
        Xs[t][d] = acc;   // in-place: only this thread touches column d
    }
    __syncthreads();

    // LayerNorm: one warp per 8 rows.
    int w = tid >> 5, lane = tid & 31;
    float g[8], bt[8];
    #pragma unroll
    for (int k = 0; k < 8; k++) {
        g[k]  = gamma[lane + 32 * k];
        bt[k] = beta[lane + 32 * k];
    }
    #pragma unroll
    for (int r = 0; r < 8; r++) {
        int t = w * 8 + r;
        float yv[8];
        float s1 = 0.f, s2 = 0.f;
        #pragma unroll
        for (int k = 0; k < 8; k++) {
            float y = Xs[t][lane + 32 * k];
            yv[k] = y;
            s1 += y;
            s2 = fmaf(y, y, s2);
        }
        #pragma unroll
        for (int off = 16; off > 0; off >>= 1) {
            s1 += __shfl_xor_sync(0xffffffffu, s1, off);
            s2 += __shfl_xor_sync(0xffffffffu, s2, off);
        }
        float mu  = s1 * (1.f / Dn);
        float var = s2 * (1.f / Dn) - mu * mu;
        float rs  = rsqrtf(var + EPSc);
        float* orow = out + ((size_t)b * Sn + (size_t)(c * Ln + t)) * Dn;
        #pragma unroll
        for (int k = 0; k < 8; k++) {
            orow[lane + 32 * k] = fmaf((yv[k] - mu) * rs, g[k], bt[k]);
        }
    }
}

extern "C" void kernel_launch(void* const* d_in, const int* in_sizes, int n_in,
                              void* d_out, int out_size) {
    (void)in_sizes; (void)n_in; (void)out_size;
    const float* x     = (const float*)d_in[0];
    const float* A     = (const float*)d_in[1];
    const float* Bm    = (const float*)d_in[2];
    const float* Cm    = (const float*)d_in[3];
    const float* Dv    = (const float*)d_in[4];
    const float* gamma = (const float*)d_in[5];
    const float* beta  = (const float*)d_in[6];
    float* out = (float*)d_out;

    const int smem1 = (Ln * (Dn + 4) + Nn * Dn + Nn * (Ln + 1) + Nn) * 4;
    const int smem3 = (Ln * (Dn + 4) + Ln * Nn + 2 * Nn) * 4;
    cudaFuncSetAttribute(s4_phase1, cudaFuncAttributeMaxDynamicSharedMemorySize, smem1);
    cudaFuncSetAttribute(s4_phase3, cudaFuncAttributeMaxDynamicSharedMemorySize, smem3);

    s4_phase1<<<Bn * Cn, 256, smem1>>>(x, A, Bm);
    s4_phase2<<<1, 256>>>(A);
    s4_phase3<<<Bn * Cn, 256, smem3>>>(x, A, Cm, Dv, gamma, beta, out);
}

// round 11
// speedup vs baseline: 1.2018x; 1.2018x over previous
#include <cuda_runtime.h>
#include <math.h>

#define Bn 16
#define Sn 4096
#define Dn 256
#define Nn 16
#define Ln 64
#define Cn (Sn / Ln)   // 64 chunks
#define DTc 1e-4f
#define EPSc 1e-5f
#define XSTRIDE (Dn + 4)   // 260: float4-aligned, conflict-free phases
#define WSTRIDE 68         // Ws row stride (float4-aligned, conflict-free GEMM stores)

// Static scratch (no allocations allowed).
// g_H layout: [b][c][t][n] (t-major so phase3 loads it with zero transpose).
__device__ float g_H[(size_t)Bn * Cn * Ln * Nn];   // 4 MB
__device__ float g_hend[Bn * Cn * Nn];

#define FMA16(u, b0, b1, b2, b3)                                   \
    a0 = fmaf((u).x, (b0).x, a0); a0 = fmaf((u).y, (b0).y, a0);    \
    a0 = fmaf((u).z, (b0).z, a0); a0 = fmaf((u).w, (b0).w, a0);    \
    a1 = fmaf((u).x, (b1).x, a1); a1 = fmaf((u).y, (b1).y, a1);    \
    a1 = fmaf((u).z, (b1).z, a1); a1 = fmaf((u).w, (b1).w, a1);    \
    a2 = fmaf((u).x, (b2).x, a2); a2 = fmaf((u).y, (b2).y, a2);    \
    a2 = fmaf((u).z, (b2).z, a2); a2 = fmaf((u).w, (b2).w, a2);    \
    a3 = fmaf((u).x, (b3).x, a3); a3 = fmaf((u).y, (b3).y, a3);    \
    a3 = fmaf((u).z, (b3).z, a3); a3 = fmaf((u).w, (b3).w, a3)

// ---------------------------------------------------------------------------
// Phase 1: per (batch, chunk). W = B_d @ U (16 x 64 over D=256), local scan,
// store local H ([t][n] layout) + chunk-final state.
// ---------------------------------------------------------------------------
__global__ __launch_bounds__(256, 2) void s4_phase1(const float* __restrict__ x,
                                                    const float* __restrict__ A,
                                                    const float* __restrict__ Bm) {
    extern __shared__ float smem[];
    float (*Xs)[XSTRIDE] = (float(*)[XSTRIDE])smem;                     // 64 x 260
    float (*Bs)[Dn]      = (float(*)[Dn])(smem + Ln * XSTRIDE);         // 16 x 256
    float (*Ws)[WSTRIDE] = (float(*)[WSTRIDE])(smem + Ln * XSTRIDE + Nn * Dn);
    float* Ad            = smem + Ln * XSTRIDE + Nn * Dn + Nn * WSTRIDE;

    int blk = blockIdx.x;
    int b = blk / Cn, c = blk % Cn;
    int tid = threadIdx.x;

    // Stage x chunk (64KB contiguous) into padded smem, float4, MLP=16.
    const float4* xg = (const float4*)(x + ((size_t)b * Sn + (size_t)c * Ln) * Dn);
    #pragma unroll
    for (int k = 0; k < 16; k++) {
        int i4 = tid + k * 256;
        int t = i4 >> 6, d4 = i4 & 63;
        *(float4*)&Xs[t][d4 * 4] = xg[i4];
    }
    // B_d = DT * Bm
    float* bsf = &Bs[0][0];
    #pragma unroll
    for (int k = 0; k < 16; k++) {
        int i = tid + k * 256;
        bsf[i] = DTc * Bm[i];
    }
    if (tid < Nn) Ad[tid] = (float)exp(-(double)DTc * fabs((double)A[tid]));
    __syncthreads();

    // GEMM1: thread = (n-quad, t). Software-pipelined: prefetch iter d4+1's
    // u (conflict-free LDS.128) and 4 B rows (warp-broadcast LDS.128) while
    // issuing iter d4's 16 FMAs (32 issue cyc > 29 cyc LDS latency).
    int t  = tid & 63;
    int n0 = (tid >> 6) * 4;
    const float4* up = (const float4*)&Xs[t][0];
    const float4* bp = (const float4*)&Bs[n0][0];   // rows are 64 float4 apart
    float a0 = 0.f, a1 = 0.f, a2 = 0.f, a3 = 0.f;
    float4 u  = up[0];
    float4 b0 = bp[0], b1 = bp[64], b2 = bp[128], b3 = bp[192];
    #pragma unroll 7
    for (int d4 = 0; d4 < 63; d4++) {
        float4 un  = up[d4 + 1];
        float4 b0n = bp[d4 + 1];
        float4 b1n = bp[d4 + 65];
        float4 b2n = bp[d4 + 129];
        float4 b3n = bp[d4 + 193];
        FMA16(u, b0, b1, b2, b3);
        u = un; b0 = b0n; b1 = b1n; b2 = b2n; b3 = b3n;
    }
    FMA16(u, b0, b1, b2, b3);
    Ws[n0 + 0][t] = a0;
    Ws[n0 + 1][t] = a1;
    Ws[n0 + 2][t] = a2;
    Ws[n0 + 3][t] = a3;
    __syncthreads();

    // Local scan (16 lanes, sequential over L=64; tiny).
    if (tid < Nn) {
        int n = tid;
        float a = Ad[n], h = 0.f;
        #pragma unroll
        for (int tt = 0; tt < Ln; tt++) {
            h = fmaf(a, h, Ws[n][tt]);
            Ws[n][tt] = h;
        }
        g_hend[(b * Cn + c) * Nn + n] = h;
    }
    __syncthreads();

    // Copy-out H in [t][n] order (coalesced global, minor smem conflicts).
    size_t base = ((size_t)(b * Cn + c)) * Ln * Nn;
    #pragma unroll
    for (int k = 0; k < 4; k++) {
        int i = tid + k * 256;
        int tt = i >> 4, n = i & 15;
        g_H[base + i] = Ws[n][tt];
    }
}

// ---------------------------------------------------------------------------
// Phase 3: per (batch, chunk). Recompute hstart from g_hend (phase2 folded
// in), correct H (clip), Y = Cm @ H + Dv .* U (clip), LayerNorm, write out.
// ---------------------------------------------------------------------------
__global__ __launch_bounds__(256, 3) void s4_phase3(const float* __restrict__ x,
                                                    const float* __restrict__ A,
                                                    const float* __restrict__ Cm,
                                                    const float* __restrict__ Dv,
                                                    const float* __restrict__ gamma,
                                                    const float* __restrict__ beta,
                                                    float* __restrict__ out) {
    extern __shared__ float smem[];
    float (*Xs)[XSTRIDE] = (float(*)[XSTRIDE])smem;                 // 64 x 260
    float (*Ht)[Nn]      = (float(*)[Nn])(smem + Ln * XSTRIDE);     // 64 x 16 [t][n]

    int blk = blockIdx.x;
    int b = blk / Cn, c = blk % Cn;
    int tid = threadIdx.x;

    const float4* xg = (const float4*)(x + ((size_t)b * Sn + (size_t)c * Ln) * Dn);
    #pragma unroll
    for (int k = 0; k < 16; k++) {
        int i4 = tid + k * 256;
        int t = i4 >> 6, d4 = i4 & 63;
        *(float4*)&Xs[t][d4 * 4] = xg[i4];
    }
    // g_H already [t][n]: straight float4 copy, conflict-free.
    {
        const float4* hg = (const float4*)(g_H + ((size_t)(b * Cn + c)) * Ln * Nn);
        ((float4*)&Ht[0][0])[tid] = hg[tid];
    }
    __syncthreads();

    // hstart scan (phase2 folded in) + correction, 16 lanes.
    // Identical FMA ordering to the old phase2 -> bit-identical result.
    if (tid < Nn) {
        int n = tid;
        float a = (float)exp(-(double)DTc * fabs((double)A[n]));
        float aL = a;
        #pragma unroll
        for (int i = 0; i < 6; i++) aL *= aL;    // a^64
        const float* he = g_hend + b * Cn * Nn + n;
        float s = 0.f;
        for (int cc = 0; cc < c; cc++) s = fmaf(aL, s, he[cc * Nn]);
        float p = a;
        #pragma unroll
        for (int tt = 0; tt < Ln; tt++) {
            float v = fmaf(p, s, Ht[tt][n]);
            v = fminf(fmaxf(v, -10.f), 10.f);
            Ht[tt][n] = v;
            p *= a;
        }
    }
    __syncthreads();

    // GEMM2: thread = d. Cm row in regs; Ht rows are warp-broadcast LDS.128.
    // Pipelined: prefetch t+1's h-row + u while issuing t's 17 FMAs.
    int d = tid;
    const float4* cmp = (const float4*)(Cm + d * Nn);
    float4 c0 = cmp[0], c1 = cmp[1], c2 = cmp[2], c3 = cmp[3];
    float dv = Dv[d];
    const float4* hp = (const float4*)&Ht[0][0];   // 4 float4 per t
    float4 h0 = hp[0], h1 = hp[1], h2 = hp[2], h3 = hp[3];
    float u = Xs[0][d];
    #pragma unroll 7
    for (int t = 0; t < 63; t++) {
        float4 h0n = hp[4 * t + 4], h1n = hp[4 * t + 5];
        float4 h2n = hp[4 * t + 6], h3n = hp[4 * t + 7];
        float un = Xs[t + 1][d];
        float acc = u * dv;
        acc = fmaf(c0.x, h0.x, acc); acc = fmaf(c0.y, h0.y, acc);
        acc = fmaf(c0.z, h0.z, acc); acc = fmaf(c0.w, h0.w, acc);
        acc = fmaf(c1.x, h1.x, acc); acc = fmaf(c1.y, h1.y, acc);
        acc = fmaf(c1.z, h1.z, acc); acc = fmaf(c1.w, h1.w, acc);
        acc = fmaf(c2.x, h2.x, acc); acc = fmaf(c2.y, h2.y, acc);
        acc = fmaf(c2.z, h2.z, acc); acc = fmaf(c2.w, h2.w, acc);
        acc = fmaf(c3.x, h3.x, acc); acc = fmaf(c3.y, h3.y, acc);
        acc = fmaf(c3.z, h3.z, acc); acc = fmaf(c3.w, h3.w, acc);
        acc = fminf(fmaxf(acc, -10.f), 10.f);
        Xs[t][d] = acc;
        u = un; h0 = h0n; h1 = h1n; h2 = h2n; h3 = h3n;
    }
    {
        float acc = u * dv;
        acc = fmaf(c0.x, h0.x, acc); acc = fmaf(c0.y, h0.y, acc);
        acc = fmaf(c0.z, h0.z, acc); acc = fmaf(c0.w, h0.w, acc);
        acc = fmaf(c1.x, h1.x, acc); acc = fmaf(c1.y, h1.y, acc);
        acc = fmaf(c1.z, h1.z, acc); acc = fmaf(c1.w, h1.w, acc);
        acc = fmaf(c2.x, h2.x, acc); acc = fmaf(c2.y, h2.y, acc);
        acc = fmaf(c2.z, h2.z, acc); acc = fmaf(c2.w, h2.w, acc);
        acc = fmaf(c3.x, h3.x, acc); acc = fmaf(c3.y, h3.y, acc);
        acc = fmaf(c3.z, h3.z, acc); acc = fmaf(c3.w, h3.w, acc);
        acc = fminf(fmaxf(acc, -10.f), 10.f);
        Xs[63][d] = acc;
    }
    __syncthreads();

    // LayerNorm: one warp per 8 rows.
    int w = tid >> 5, lane = tid & 31;
    float g[8], bt[8];
    #pragma unroll
    for (int k = 0; k < 8; k++) {
        g[k]  = gamma[lane + 32 * k];
        bt[k] = beta[lane + 32 * k];
    }
    #pragma unroll
    for (int r = 0; r < 8; r++) {
        int t = w * 8 + r;
        float yv[8];
        float s1 = 0.f, s2 = 0.f;
        #pragma unroll
        for (int k = 0; k < 8; k++) {
            float y = Xs[t][lane + 32 * k];
            yv[k] = y;
            s1 += y;
            s2 = fmaf(y, y, s2);
        }
        #pragma unroll
        for (int off = 16; off > 0; off >>= 1) {
            s1 += __shfl_xor_sync(0xffffffffu, s1, off);
            s2 += __shfl_xor_sync(0xffffffffu, s2, off);
        }
        float mu  = s1 * (1.f / Dn);
        float var = s2 * (1.f / Dn) - mu * mu;
        float rs  = rsqrtf(var + EPSc);
        float* orow = out + ((size_t)b * Sn + (size_t)(c * Ln + t)) * Dn;
        #pragma unroll
        for (int k = 0; k < 8; k++) {
            orow[lane + 32 * k] = fmaf((yv[k] - mu) * rs, g[k], bt[k]);
        }
    }
}

extern "C" void kernel_launch(void* const* d_in, const int* in_sizes, int n_in,
                              void* d_out, int out_size) {
    (void)in_sizes; (void)n_in; (void)out_size;
    const float* x     = (const float*)d_in[0];
    const float* A     = (const float*)d_in[1];
    const float* Bm    = (const float*)d_in[2];
    const float* Cm    = (const float*)d_in[3];
    const float* Dv    = (const float*)d_in[4];
    const float* gamma = (const float*)d_in[5];
    const float* beta  = (const float*)d_in[6];
    float* out = (float*)d_out;

    const int smem1 = (Ln * XSTRIDE + Nn * Dn + Nn * WSTRIDE + Nn) * 4;   // ~87.4 KB
    const int smem3 = (Ln * XSTRIDE + Ln * Nn) * 4;                       // ~70.7 KB
    cudaFuncSetAttribute(s4_phase1, cudaFuncAttributeMaxDynamicSharedMemorySize, smem1);
    cudaFuncSetAttribute(s4_phase3, cudaFuncAttributeMaxDynamicSharedMemorySize, smem3);

    s4_phase1<<<Bn * Cn, 256, smem1>>>(x, A, Bm);
    s4_phase3<<<Bn * Cn, 256, smem3>>>(x, A, Cm, Dv, gamma, beta, out);
}

// round 12
// speedup vs baseline: 1.2668x; 1.0541x over previous
#include <cuda_runtime.h>
#include <math.h>

#define Bn 16
#define Sn 4096
#define Dn 256
#define Nn 16
#define Ln 64
#define Cn (Sn / Ln)   // 64 chunks
#define DTc 1e-4f
#define EPSc 1e-5f
#define X1S 132        // phase1 staged half-row stride (float4-aligned, conflict-free)
#define YS 257         // phase3 output buffer stride (conflict-free for t/d access)
#define WSTRIDE 68

// Static scratch. g_H layout: [b][c][t][n] (t-major: phase3 loads with no transpose).
__device__ float g_H[(size_t)Bn * Cn * Ln * Nn];   // 4 MB
__device__ float g_hend[Bn * Cn * Nn];
__device__ float g_hstart[Bn * Cn * Nn];

#define FMA16(u, b0, b1, b2, b3)                                   \
    a0 = fmaf((u).x, (b0).x, a0); a0 = fmaf((u).y, (b0).y, a0);    \
    a0 = fmaf((u).z, (b0).z, a0); a0 = fmaf((u).w, (b0).w, a0);    \
    a1 = fmaf((u).x, (b1).x, a1); a1 = fmaf((u).y, (b1).y, a1);    \
    a1 = fmaf((u).z, (b1).z, a1); a1 = fmaf((u).w, (b1).w, a1);    \
    a2 = fmaf((u).x, (b2).x, a2); a2 = fmaf((u).y, (b2).y, a2);    \
    a2 = fmaf((u).z, (b2).z, a2); a2 = fmaf((u).w, (b2).w, a2);    \
    a3 = fmaf((u).x, (b3).x, a3); a3 = fmaf((u).y, (b3).y, a3);    \
    a3 = fmaf((u).z, (b3).z, a3); a3 = fmaf((u).w, (b3).w, a3)

// ---------------------------------------------------------------------------
// Phase 1: per (batch, chunk). W = B_d @ U over D=256 done in two 128-wide
// passes (same accumulation order -> bit-identical), halving smem so 4 CTAs/SM
// fit. Then local scan, store H ([t][n]) + chunk-final state.
// ---------------------------------------------------------------------------
__global__ __launch_bounds__(256, 4) void s4_phase1(const float* __restrict__ x,
                                                    const float* __restrict__ A,
                                                    const float* __restrict__ Bm) {
    extern __shared__ float smem[];
    float (*Xh)[X1S]     = (float(*)[X1S])smem;                       // 64 x 132
    float (*Bs)[Dn]      = (float(*)[Dn])(smem + Ln * X1S);           // 16 x 256
    float (*Ws)[WSTRIDE] = (float(*)[WSTRIDE])(smem + Ln * X1S + Nn * Dn);
    float* Ad            = smem + Ln * X1S + Nn * Dn + Nn * WSTRIDE;

    int blk = blockIdx.x;
    int b = blk / Cn, c = blk % Cn;
    int tid = threadIdx.x;

    // B_d = DT * Bm (full), once.
    float* bsf = &Bs[0][0];
    #pragma unroll
    for (int k = 0; k < 16; k++) {
        int i = tid + k * 256;
        bsf[i] = DTc * Bm[i];
    }
    if (tid < Nn) Ad[tid] = (float)exp(-(double)DTc * fabs((double)A[tid]));

    const float4* xg = (const float4*)(x + ((size_t)b * Sn + (size_t)c * Ln) * Dn);
    int t  = tid & 63;
    int n0 = (tid >> 6) * 4;
    float a0 = 0.f, a1 = 0.f, a2 = 0.f, a3 = 0.f;

    #pragma unroll
    for (int p = 0; p < 2; p++) {
        __syncthreads();   // Bs ready (p=0) / prior GEMM reads done (p=1)
        // Stage half of x chunk: cols [128p, 128p+128).
        #pragma unroll
        for (int k = 0; k < 8; k++) {
            int i4 = tid + k * 256;
            int tt = i4 >> 5, d4 = i4 & 31;
            *(float4*)&Xh[tt][d4 * 4] = xg[tt * 64 + p * 32 + d4];
        }
        __syncthreads();

        // GEMM half, software-pipelined (prefetch next u + 4 B rows).
        const float4* up = (const float4*)&Xh[t][0];
        const float4* bq = (const float4*)&Bs[n0][0] + p * 32;   // rows 64 f4 apart
        float4 u  = up[0];
        float4 b0 = bq[0], b1 = bq[64], b2 = bq[128], b3 = bq[192];
        #pragma unroll
        for (int j = 0; j < 31; j++) {
            float4 un  = up[j + 1];
            float4 b0n = bq[j + 1];
            float4 b1n = bq[j + 65];
            float4 b2n = bq[j + 129];
            float4 b3n = bq[j + 193];
            FMA16(u, b0, b1, b2, b3);
            u = un; b0 = b0n; b1 = b1n; b2 = b2n; b3 = b3n;
        }
        FMA16(u, b0, b1, b2, b3);
    }
    Ws[n0 + 0][t] = a0;
    Ws[n0 + 1][t] = a1;
    Ws[n0 + 2][t] = a2;
    Ws[n0 + 3][t] = a3;
    __syncthreads();

    // Local scan (16 lanes, L=64).
    if (tid < Nn) {
        int n = tid;
        float a = Ad[n], h = 0.f;
        #pragma unroll
        for (int tt = 0; tt < Ln; tt++) {
            h = fmaf(a, h, Ws[n][tt]);
            Ws[n][tt] = h;
        }
        g_hend[(b * Cn + c) * Nn + n] = h;
    }
    __syncthreads();

    // Copy-out H in [t][n] order (coalesced global).
    size_t base = ((size_t)(b * Cn + c)) * Ln * Nn;
    #pragma unroll
    for (int k = 0; k < 4; k++) {
        int i = tid + k * 256;
        int tt = i >> 4, n = i & 15;
        g_H[base + i] = Ws[n][tt];
    }
}

// ---------------------------------------------------------------------------
// Phase 2: scan across chunks. One block, 256 threads = (b, n).
// ---------------------------------------------------------------------------
__global__ __launch_bounds__(256) void s4_phase2(const float* __restrict__ A) {
    int tid = threadIdx.x;
    int b = tid >> 4, n = tid & 15;
    float a = (float)exp(-(double)DTc * fabs((double)A[n]));
    float aL = a;
    #pragma unroll
    for (int i = 0; i < 6; i++) aL *= aL;   // a^64

    float he[Cn];
    #pragma unroll
    for (int c = 0; c < Cn; c++) he[c] = g_hend[(b * Cn + c) * Nn + n];
    float s = 0.f;
    #pragma unroll
    for (int c = 0; c < Cn; c++) {
        g_hstart[(b * Cn + c) * Nn + n] = s;
        s = fmaf(aL, s, he[c]);
    }
}

// ---------------------------------------------------------------------------
// Phase 3: per (batch, chunk). Correct H (clip), Y = Cm @ H + Dv .* U (clip),
// LayerNorm, write out. GEMM2: 2 d per thread, warp-groups split t-halves
// (4x less Ht broadcast traffic); u read straight from global (L2-hot).
// ---------------------------------------------------------------------------
__global__ __launch_bounds__(256, 3) void s4_phase3(const float* __restrict__ x,
                                                    const float* __restrict__ A,
                                                    const float* __restrict__ Cm,
                                                    const float* __restrict__ Dv,
                                                    const float* __restrict__ gamma,
                                                    const float* __restrict__ beta,
                                                    float* __restrict__ out) {
    extern __shared__ float smem[];
    float (*Ys)[YS] = (float(*)[YS])smem;                    // 64 x 257
    float (*Ht)[Nn] = (float(*)[Nn])(smem + Ln * YS);        // 64 x 16 [t][n]

    int blk = blockIdx.x;
    int b = blk / Cn, c = blk % Cn;
    int tid = threadIdx.x;

    // Load local H ([t][n] layout): one float4 per thread, conflict-free.
    {
        const float4* hg = (const float4*)(g_H + ((size_t)(b * Cn + c)) * Ln * Nn);
        ((float4*)&Ht[0][0])[tid] = hg[tid];
    }
    __syncthreads();

    // Correction: h_t = clip(H_local + A^(t+1) * hstart). 16 lanes.
    if (tid < Nn) {
        int n = tid;
        float a = (float)exp(-(double)DTc * fabs((double)A[n]));
        float s = g_hstart[(b * Cn + c) * Nn + n];
        float p = a;
        #pragma unroll
        for (int tt = 0; tt < Ln; tt++) {
            float v = fmaf(p, s, Ht[tt][n]);
            v = fminf(fmaxf(v, -10.f), 10.f);
            Ht[tt][n] = v;
            p *= a;
        }
    }
    __syncthreads();

    // GEMM2: thread handles columns d and d+128 for its 32-row t-half.
    int d  = tid & 127;
    int t0 = (tid >> 7) * 32;
    const float4* cmp = (const float4*)(Cm + d * Nn);
    const float4* emp = (const float4*)(Cm + (d + 128) * Nn);
    float4 c0 = cmp[0], c1 = cmp[1], c2 = cmp[2], c3 = cmp[3];
    float4 e0 = emp[0], e1 = emp[1], e2 = emp[2], e3 = emp[3];
    float dv0 = Dv[d], dv1 = Dv[d + 128];

    const float* xrow = x + ((size_t)b * Sn + (size_t)(c * Ln + t0)) * Dn + d;
    // 2-deep u prefetch (global, coalesced, L2-resident).
    float ua = xrow[0],          va = xrow[128];
    float ub = xrow[256],        vb = xrow[256 + 128];
    const float4* hp = (const float4*)&Ht[t0][0];
    float4 h0 = hp[0], h1 = hp[1], h2 = hp[2], h3 = hp[3];

    #pragma unroll
    for (int t = 0; t < 32; t++) {
        float uc = ua, vc = va;
        if (t < 30) { uc = xrow[(t + 2) * 256]; vc = xrow[(t + 2) * 256 + 128]; }
        int tn = (t < 31) ? t + 1 : 31;
        float4 h0n = hp[4 * tn + 0], h1n = hp[4 * tn + 1];
        float4 h2n = hp[4 * tn + 2], h3n = hp[4 * tn + 3];

        float acc = ua * dv0;
        acc = fmaf(c0.x, h0.x, acc); acc = fmaf(c0.y, h0.y, acc);
        acc = fmaf(c0.z, h0.z, acc); acc = fmaf(c0.w, h0.w, acc);
        acc = fmaf(c1.x, h1.x, acc); acc = fmaf(c1.y, h1.y, acc);
        acc = fmaf(c1.z, h1.z, acc); acc = fmaf(c1.w, h1.w, acc);
        acc = fmaf(c2.x, h2.x, acc); acc = fmaf(c2.y, h2.y, acc);
        acc = fmaf(c2.z, h2.z, acc); acc = fmaf(c2.w, h2.w, acc);
        acc = fmaf(c3.x, h3.x, acc); acc = fmaf(c3.y, h3.y, acc);
        acc = fmaf(c3.z, h3.z, acc); acc = fmaf(c3.w, h3.w, acc);
        acc = fminf(fmaxf(acc, -10.f), 10.f);
        Ys[t0 + t][d] = acc;

        float acd = va * dv1;
        acd = fmaf(e0.x, h0.x, acd); acd = fmaf(e0.y, h0.y, acd);
        acd = fmaf(e0.z, h0.z, acd); acd = fmaf(e0.w, h0.w, acd);
        acd = fmaf(e1.x, h1.x, acd); acd = fmaf(e1.y, h1.y, acd);
        acd = fmaf(e1.z, h1.z, acd); acd = fmaf(e1.w, h1.w, acd);
        acd = fmaf(e2.x, h2.x, acd); acd = fmaf(e2.y, h2.y, acd);
        acd = fmaf(e2.z, h2.z, acd); acd = fmaf(e2.w, h2.w, acd);
        acd = fmaf(e3.x, h3.x, acd); acd = fmaf(e3.y, h3.y, acd);
        acd = fmaf(e3.z, h3.z, acd); acd = fmaf(e3.w, h3.w, acd);
        acd = fminf(fmaxf(acd, -10.f), 10.f);
        Ys[t0 + t][d + 128] = acd;

        ua = ub; va = vb; ub = uc; vb = vc;
        h0 = h0n; h1 = h1n; h2 = h2n; h3 = h3n;
    }
    __syncthreads();

    // LayerNorm: one warp per 8 rows.
    int w = tid >> 5, lane = tid & 31;
    float g[8], bt[8];
    #pragma unroll
    for (int k = 0; k < 8; k++) {
        g[k]  = gamma[lane + 32 * k];
        bt[k] = beta[lane + 32 * k];
    }
    #pragma unroll
    for (int r = 0; r < 8; r++) {
        int t = w * 8 + r;
        float yv[8];
        float s1 = 0.f, s2 = 0.f;
        #pragma unroll
        for (int k = 0; k < 8; k++) {
            float y = Ys[t][lane + 32 * k];
            yv[k] = y;
            s1 += y;
            s2 = fmaf(y, y, s2);
        }
        #pragma unroll
        for (int off = 16; off > 0; off >>= 1) {
            s1 += __shfl_xor_sync(0xffffffffu, s1, off);
            s2 += __shfl_xor_sync(0xffffffffu, s2, off);
        }
        float mu  = s1 * (1.f / Dn);
        float var = s2 * (1.f / Dn) - mu * mu;
        float rs  = rsqrtf(var + EPSc);
        float* orow = out + ((size_t)b * Sn + (size_t)(c * Ln + t)) * Dn;
        #pragma unroll
        for (int k = 0; k < 8; k++) {
            orow[lane + 32 * k] = fmaf((yv[k] - mu) * rs, g[k], bt[k]);
        }
    }
}

extern "C" void kernel_launch(void* const* d_in, const int* in_sizes, int n_in,
                              void* d_out, int out_size) {
    (void)in_sizes; (void)n_in; (void)out_size;
    const float* x     = (const float*)d_in[0];
    const float* A     = (const float*)d_in[1];
    const float* Bm    = (const float*)d_in[2];
    const float* Cm    = (const float*)d_in[3];
    const float* Dv    = (const float*)d_in[4];
    const float* gamma = (const float*)d_in[5];
    const float* beta  = (const float*)d_in[6];
    float* out = (float*)d_out;

    const int smem1 = (Ln * X1S + Nn * Dn + Nn * WSTRIDE + Nn) * 4;   // ~54.6 KB
    const int smem3 = (Ln * YS + Ln * Nn) * 4;                        // ~69.9 KB
    cudaFuncSetAttribute(s4_phase1, cudaFuncAttributeMaxDynamicSharedMemorySize, smem1);
    cudaFuncSetAttribute(s4_phase3, cudaFuncAttributeMaxDynamicSharedMemorySize, smem3);

    s4_phase1<<<Bn * Cn, 256, smem1>>>(x, A, Bm);
    s4_phase2<<<1, 256>>>(A);
    s4_phase3<<<Bn * Cn, 256, smem3>>>(x, A, Cm, Dv, gamma, beta, out);
}